// round 1
// baseline (speedup 1.0000x reference)
#include <cuda_runtime.h>
#include <cstdint>

// Problem constants
#define BB   4
#define SS   2048
#define DD   1024
#define HH   16
#define DKK  64
#define MROWS (BB*SS)   // 8192

// ---------------- scratch (static device globals; no allocation) -------------
__device__ float g_qp[MROWS * DD];
__device__ float g_kp[MROWS * DD];
__device__ float g_vp[MROWS * DD];
__device__ float g_ctx[MROWS * DD];
__device__ float g_x[MROWS * DD];

// ---------------- helpers ----------------------------------------------------
__device__ __forceinline__ unsigned f2tf(float x) {
    unsigned u;
    asm("cvt.rna.tf32.f32 %0, %1;" : "=r"(u) : "f"(x));
    return u;
}

__device__ __forceinline__ void mma_tf32(float (&c)[4], const unsigned (&a)[4],
                                         const unsigned (&b)[2]) {
    asm volatile(
        "mma.sync.aligned.m16n8k8.row.col.f32.tf32.tf32.f32 "
        "{%0,%1,%2,%3}, {%4,%5,%6,%7}, {%8,%9}, {%0,%1,%2,%3};\n"
        : "+f"(c[0]), "+f"(c[1]), "+f"(c[2]), "+f"(c[3])
        : "r"(a[0]), "r"(a[1]), "r"(a[2]), "r"(a[3]), "r"(b[0]), "r"(b[1]));
}

// ---------------- GEMM: C[M,N] = A[M,K] * W[N,K]^T + bias (+ residual) -------
// Block 256 thr, tile 128x128, BK=32. Warp tile 64x32 (8 warps = 2x4).
template <bool RESID>
__device__ __forceinline__ void gemm_body(const float* __restrict__ A,
                                          const float* __restrict__ W,
                                          const float* __restrict__ bias,
                                          const float* __restrict__ R,
                                          float* __restrict__ C,
                                          int bx, int by) {
    const int K = DD, N = DD;
    __shared__ unsigned As[128][36];
    __shared__ unsigned Bs[128][36];

    const int tid  = threadIdx.x;
    const int warp = tid >> 5, lane = tid & 31;
    const int g = lane >> 2, tg = lane & 3;
    const int wm = (warp >> 2) * 64;
    const int wn = (warp & 3) * 32;
    const int bm0 = bx * 128, bn0 = by * 128;

    float acc[4][4][4];
#pragma unroll
    for (int i = 0; i < 4; i++)
#pragma unroll
        for (int j = 0; j < 4; j++)
#pragma unroll
            for (int r = 0; r < 4; r++) acc[i][j][r] = 0.f;

    float4 ra[4], rb[4];
    const int NT = K / 32;

    // prefetch tile 0
#pragma unroll
    for (int i = 0; i < 4; i++) {
        int f = tid + i * 256;
        int r = f >> 3, c = (f & 7) * 4;
        ra[i] = *reinterpret_cast<const float4*>(A + (size_t)(bm0 + r) * K + c);
        rb[i] = *reinterpret_cast<const float4*>(W + (size_t)(bn0 + r) * K + c);
    }

    for (int kt = 0; kt < NT; kt++) {
        __syncthreads();
#pragma unroll
        for (int i = 0; i < 4; i++) {
            int f = tid + i * 256;
            int r = f >> 3, c = (f & 7) * 4;
            uint4 a4, b4;
            a4.x = f2tf(ra[i].x); a4.y = f2tf(ra[i].y);
            a4.z = f2tf(ra[i].z); a4.w = f2tf(ra[i].w);
            b4.x = f2tf(rb[i].x); b4.y = f2tf(rb[i].y);
            b4.z = f2tf(rb[i].z); b4.w = f2tf(rb[i].w);
            *reinterpret_cast<uint4*>(&As[r][c]) = a4;
            *reinterpret_cast<uint4*>(&Bs[r][c]) = b4;
        }
        __syncthreads();
        if (kt + 1 < NT) {
            int k0 = (kt + 1) * 32;
#pragma unroll
            for (int i = 0; i < 4; i++) {
                int f = tid + i * 256;
                int r = f >> 3, c = (f & 7) * 4;
                ra[i] = *reinterpret_cast<const float4*>(A + (size_t)(bm0 + r) * K + k0 + c);
                rb[i] = *reinterpret_cast<const float4*>(W + (size_t)(bn0 + r) * K + k0 + c);
            }
        }
#pragma unroll
        for (int kk = 0; kk < 4; kk++) {
            unsigned af[4][4];
#pragma unroll
            for (int mf = 0; mf < 4; mf++) {
                int rr = wm + mf * 16;
                af[mf][0] = As[rr + g][kk * 8 + tg];
                af[mf][1] = As[rr + g + 8][kk * 8 + tg];
                af[mf][2] = As[rr + g][kk * 8 + tg + 4];
                af[mf][3] = As[rr + g + 8][kk * 8 + tg + 4];
            }
#pragma unroll
            for (int nf = 0; nf < 4; nf++) {
                unsigned bf[2];
                int cc = wn + nf * 8;
                bf[0] = Bs[cc + g][kk * 8 + tg];
                bf[1] = Bs[cc + g][kk * 8 + tg + 4];
#pragma unroll
                for (int mf = 0; mf < 4; mf++) mma_tf32(acc[mf][nf], af[mf], bf);
            }
        }
    }

    // epilogue
#pragma unroll
    for (int mf = 0; mf < 4; mf++) {
        int r0 = bm0 + wm + mf * 16 + g;
        int r1 = r0 + 8;
#pragma unroll
        for (int nf = 0; nf < 4; nf++) {
            int cc = bn0 + wn + nf * 8 + 2 * tg;
            float b0 = bias[cc], b1 = bias[cc + 1];
            float v00 = acc[mf][nf][0] + b0;
            float v01 = acc[mf][nf][1] + b1;
            float v10 = acc[mf][nf][2] + b0;
            float v11 = acc[mf][nf][3] + b1;
            if (RESID) {
                float2 q0 = *reinterpret_cast<const float2*>(R + (size_t)r0 * N + cc);
                float2 q1 = *reinterpret_cast<const float2*>(R + (size_t)r1 * N + cc);
                v00 += q0.x; v01 += q0.y; v10 += q1.x; v11 += q1.y;
            }
            *reinterpret_cast<float2*>(C + (size_t)r0 * N + cc) = make_float2(v00, v01);
            *reinterpret_cast<float2*>(C + (size_t)r1 * N + cc) = make_float2(v10, v11);
        }
    }
}

__global__ void __launch_bounds__(256) qkv_kernel(
    const float* __restrict__ q, const float* __restrict__ k, const float* __restrict__ v,
    const float* __restrict__ Wq, const float* __restrict__ Wk, const float* __restrict__ Wv,
    const float* __restrict__ bq, const float* __restrict__ bk, const float* __restrict__ bv) {
    int z = blockIdx.z;
    const float* A = (z == 0) ? q : (z == 1) ? k : v;
    const float* W = (z == 0) ? Wq : (z == 1) ? Wk : Wv;
    const float* b = (z == 0) ? bq : (z == 1) ? bk : bv;
    float* C = (z == 0) ? g_qp : (z == 1) ? g_kp : g_vp;
    gemm_body<false>(A, W, b, nullptr, C, blockIdx.x, blockIdx.y);
}

__global__ void __launch_bounds__(256) oproj_kernel(const float* __restrict__ q,
                                                    const float* __restrict__ Wo,
                                                    const float* __restrict__ bo) {
    gemm_body<true>(g_ctx, Wo, bo, q, g_x, blockIdx.x, blockIdx.y);
}

// ---------------- Flash attention over contiguous [2048,64] views ------------
// Block: 256 thr (8 warps), Q tile = 128 rows, K tile = 64 keys, DK = 64.
// Warp w handles q-rows [w*16, w*16+16).
#define LDQ 68
#define ATT_SMEM_WORDS ((128 + 64 + 64 + 128) * LDQ)

__global__ void __launch_bounds__(256) attn_kernel() {
    extern __shared__ unsigned sm[];
    unsigned* Qs = sm;                       // [128][68]
    unsigned* Ks = sm + 128 * LDQ;           // [64][68]
    unsigned* Vs = sm + (128 + 64) * LDQ;    // [64][68]
    unsigned* Ps = sm + (128 + 128) * LDQ;   // [128][68]

    const int bh = blockIdx.y;
    const int qt = blockIdx.x;
    const float* qb = g_qp + (size_t)bh * SS * DKK;
    const float* kb = g_kp + (size_t)bh * SS * DKK;
    const float* vb = g_vp + (size_t)bh * SS * DKK;
    float* ob = g_ctx + (size_t)bh * SS * DKK;

    const int tid = threadIdx.x;
    const int warp = tid >> 5, lane = tid & 31;
    const int g = lane >> 2, tg = lane & 3;
    const int rr = warp * 16;

    // Load Q tile: rows qt*128 .. +127, 64 cols
#pragma unroll
    for (int i = 0; i < 8; i++) {
        int f = tid + i * 256;          // 2048 float4
        int r = f >> 4, c = (f & 15) * 4;
        float4 qv = *reinterpret_cast<const float4*>(qb + (size_t)(qt * 128 + r) * DKK + c);
        Qs[r * LDQ + c + 0] = f2tf(qv.x);
        Qs[r * LDQ + c + 1] = f2tf(qv.y);
        Qs[r * LDQ + c + 2] = f2tf(qv.z);
        Qs[r * LDQ + c + 3] = f2tf(qv.w);
    }

    float o[8][4];
#pragma unroll
    for (int nf = 0; nf < 8; nf++)
#pragma unroll
        for (int r = 0; r < 4; r++) o[nf][r] = 0.f;
    float rmax0 = -1e30f, rmax1 = -1e30f, rsum0 = 0.f, rsum1 = 0.f;
    const float scale = 0.125f;   // 1/sqrt(64)

    for (int kt = 0; kt < SS / 64; kt++) {
        __syncthreads();
        // Load K,V tiles: 64 keys x 64
#pragma unroll
        for (int i = 0; i < 4; i++) {
            int f = tid + i * 256;      // 1024 float4
            int r = f >> 4, c = (f & 15) * 4;
            float4 kv = *reinterpret_cast<const float4*>(kb + (size_t)(kt * 64 + r) * DKK + c);
            float4 vv = *reinterpret_cast<const float4*>(vb + (size_t)(kt * 64 + r) * DKK + c);
            Ks[r * LDQ + c + 0] = f2tf(kv.x); Ks[r * LDQ + c + 1] = f2tf(kv.y);
            Ks[r * LDQ + c + 2] = f2tf(kv.z); Ks[r * LDQ + c + 3] = f2tf(kv.w);
            Vs[r * LDQ + c + 0] = f2tf(vv.x); Vs[r * LDQ + c + 1] = f2tf(vv.y);
            Vs[r * LDQ + c + 2] = f2tf(vv.z); Vs[r * LDQ + c + 3] = f2tf(vv.w);
        }
        __syncthreads();

        // S = Q*K^T  (m16 x n64 x k64 per warp)
        float s[8][4];
#pragma unroll
        for (int nf = 0; nf < 8; nf++)
#pragma unroll
            for (int r = 0; r < 4; r++) s[nf][r] = 0.f;
#pragma unroll
        for (int kk = 0; kk < 8; kk++) {
            unsigned af[4];
            af[0] = Qs[(rr + g) * LDQ + kk * 8 + tg];
            af[1] = Qs[(rr + g + 8) * LDQ + kk * 8 + tg];
            af[2] = Qs[(rr + g) * LDQ + kk * 8 + tg + 4];
            af[3] = Qs[(rr + g + 8) * LDQ + kk * 8 + tg + 4];
#pragma unroll
            for (int nf = 0; nf < 8; nf++) {
                unsigned bf[2];
                bf[0] = Ks[(nf * 8 + g) * LDQ + kk * 8 + tg];
                bf[1] = Ks[(nf * 8 + g) * LDQ + kk * 8 + tg + 4];
                mma_tf32(s[nf], af, bf);
            }
        }

        // online softmax (rows g, g+8 of this warp's slab)
#pragma unroll
        for (int nf = 0; nf < 8; nf++) {
            s[nf][0] *= scale; s[nf][1] *= scale;
            s[nf][2] *= scale; s[nf][3] *= scale;
        }
        float m0 = -1e30f, m1 = -1e30f;
#pragma unroll
        for (int nf = 0; nf < 8; nf++) {
            m0 = fmaxf(m0, fmaxf(s[nf][0], s[nf][1]));
            m1 = fmaxf(m1, fmaxf(s[nf][2], s[nf][3]));
        }
        m0 = fmaxf(m0, __shfl_xor_sync(0xffffffffu, m0, 1));
        m0 = fmaxf(m0, __shfl_xor_sync(0xffffffffu, m0, 2));
        m1 = fmaxf(m1, __shfl_xor_sync(0xffffffffu, m1, 1));
        m1 = fmaxf(m1, __shfl_xor_sync(0xffffffffu, m1, 2));
        float nm0 = fmaxf(rmax0, m0), nm1 = fmaxf(rmax1, m1);
        float al0 = __expf(rmax0 - nm0), al1 = __expf(rmax1 - nm1);
        rmax0 = nm0; rmax1 = nm1;

        float l0 = 0.f, l1 = 0.f;
#pragma unroll
        for (int nf = 0; nf < 8; nf++) {
            float p00 = __expf(s[nf][0] - nm0);
            float p01 = __expf(s[nf][1] - nm0);
            float p10 = __expf(s[nf][2] - nm1);
            float p11 = __expf(s[nf][3] - nm1);
            l0 += p00 + p01; l1 += p10 + p11;
            int cc = nf * 8 + 2 * tg;
            Ps[(rr + g) * LDQ + cc] = f2tf(p00);
            Ps[(rr + g) * LDQ + cc + 1] = f2tf(p01);
            Ps[(rr + g + 8) * LDQ + cc] = f2tf(p10);
            Ps[(rr + g + 8) * LDQ + cc + 1] = f2tf(p11);
        }
        l0 += __shfl_xor_sync(0xffffffffu, l0, 1);
        l0 += __shfl_xor_sync(0xffffffffu, l0, 2);
        l1 += __shfl_xor_sync(0xffffffffu, l1, 1);
        l1 += __shfl_xor_sync(0xffffffffu, l1, 2);
        rsum0 = rsum0 * al0 + l0;
        rsum1 = rsum1 * al1 + l1;
#pragma unroll
        for (int nf = 0; nf < 8; nf++) {
            o[nf][0] *= al0; o[nf][1] *= al0;
            o[nf][2] *= al1; o[nf][3] *= al1;
        }
        __syncwarp();

        // O += P*V  (m16 x n64(dk) x k64(keys))
#pragma unroll
        for (int kk = 0; kk < 8; kk++) {
            unsigned af[4];
            af[0] = Ps[(rr + g) * LDQ + kk * 8 + tg];
            af[1] = Ps[(rr + g + 8) * LDQ + kk * 8 + tg];
            af[2] = Ps[(rr + g) * LDQ + kk * 8 + tg + 4];
            af[3] = Ps[(rr + g + 8) * LDQ + kk * 8 + tg + 4];
#pragma unroll
            for (int nf = 0; nf < 8; nf++) {
                unsigned bf[2];
                bf[0] = Vs[(kk * 8 + tg) * LDQ + nf * 8 + g];
                bf[1] = Vs[(kk * 8 + tg + 4) * LDQ + nf * 8 + g];
                mma_tf32(o[nf], af, bf);
            }
        }
    }

    // write ctx
    float inv0 = 1.f / rsum0, inv1 = 1.f / rsum1;
    int r0 = qt * 128 + rr + g;
    int r1 = r0 + 8;
#pragma unroll
    for (int nf = 0; nf < 8; nf++) {
        int cc = nf * 8 + 2 * tg;
        *reinterpret_cast<float2*>(ob + (size_t)r0 * DKK + cc) =
            make_float2(o[nf][0] * inv0, o[nf][1] * inv0);
        *reinterpret_cast<float2*>(ob + (size_t)r1 * DKK + cc) =
            make_float2(o[nf][2] * inv1, o[nf][3] * inv1);
    }
}

// ---------------- LayerNorm ---------------------------------------------------
__global__ void __launch_bounds__(256) ln_kernel(const float* __restrict__ gamma,
                                                 const float* __restrict__ beta,
                                                 float* __restrict__ out) {
    __shared__ float red[16];
    const int row = blockIdx.x;
    const int tid = threadIdx.x;
    const float* xr = g_x + (size_t)row * DD;
    float4 xv = *reinterpret_cast<const float4*>(xr + tid * 4);
    float s = xv.x + xv.y + xv.z + xv.w;
    float q2 = xv.x * xv.x + xv.y * xv.y + xv.z * xv.z + xv.w * xv.w;
#pragma unroll
    for (int off = 16; off > 0; off >>= 1) {
        s += __shfl_xor_sync(0xffffffffu, s, off);
        q2 += __shfl_xor_sync(0xffffffffu, q2, off);
    }
    int warp = tid >> 5, lane = tid & 31;
    if (lane == 0) { red[warp] = s; red[8 + warp] = q2; }
    __syncthreads();
    if (tid < 32) {
        float ss = (tid < 8) ? red[tid] : 0.f;
        float qq = (tid < 8) ? red[8 + tid] : 0.f;
#pragma unroll
        for (int off = 4; off > 0; off >>= 1) {
            ss += __shfl_xor_sync(0xffffffffu, ss, off);
            qq += __shfl_xor_sync(0xffffffffu, qq, off);
        }
        if (tid == 0) { red[0] = ss; red[1] = qq; }
    }
    __syncthreads();
    float mean = red[0] * (1.f / (float)DD);
    float var = red[1] * (1.f / (float)DD) - mean * mean;
    float inv = rsqrtf(var + 1e-6f);
    int c = tid * 4;
    float4 gv = *reinterpret_cast<const float4*>(gamma + c);
    float4 bv = *reinterpret_cast<const float4*>(beta + c);
    float4 ov;
    ov.x = (xv.x - mean) * inv * gv.x + bv.x;
    ov.y = (xv.y - mean) * inv * gv.y + bv.y;
    ov.z = (xv.z - mean) * inv * gv.z + bv.z;
    ov.w = (xv.w - mean) * inv * gv.w + bv.w;
    *reinterpret_cast<float4*>(out + (size_t)row * DD + c) = ov;
}

// ---------------- launch ------------------------------------------------------
extern "C" void kernel_launch(void* const* d_in, const int* in_sizes, int n_in,
                              void* d_out, int out_size) {
    const float* q     = (const float*)d_in[0];
    const float* k     = (const float*)d_in[1];
    const float* v     = (const float*)d_in[2];
    const float* Wq    = (const float*)d_in[3];
    const float* bq    = (const float*)d_in[4];
    const float* Wk    = (const float*)d_in[5];
    const float* bk    = (const float*)d_in[6];
    const float* Wv    = (const float*)d_in[7];
    const float* bv    = (const float*)d_in[8];
    const float* Wo    = (const float*)d_in[9];
    const float* bo    = (const float*)d_in[10];
    const float* gamma = (const float*)d_in[11];
    const float* beta  = (const float*)d_in[12];
    float* out = (float*)d_out;

    static const size_t att_smem = (size_t)ATT_SMEM_WORDS * 4;  // 104448 B
    cudaFuncSetAttribute(attn_kernel, cudaFuncAttributeMaxDynamicSharedMemorySize,
                         (int)att_smem);

    qkv_kernel<<<dim3(64, 8, 3), 256>>>(q, k, v, Wq, Wk, Wv, bq, bk, bv);
    attn_kernel<<<dim3(SS / 128, BB * HH), 256, att_smem>>>();
    oproj_kernel<<<dim3(64, 8), 256>>>(q, Wo, bo);
    ln_kernel<<<MROWS, 256>>>(gamma, beta, out);
}

// round 2
// speedup vs baseline: 2.0644x; 2.0644x over previous
#include <cuda_runtime.h>
#include <cuda_bf16.h>
#include <cstdint>

#define BB   4
#define SS   2048
#define DD   1024
#define HH   16
#define DKK  64
#define MROWS (BB*SS)   // 8192

// ---------------- scratch ----------------------------------------------------
__device__ __align__(128) __nv_bfloat16 g_qp[MROWS * DD];
__device__ __align__(128) __nv_bfloat16 g_kp[MROWS * DD];
__device__ __align__(128) __nv_bfloat16 g_vp[MROWS * DD];
__device__ __align__(128) __nv_bfloat16 g_ctx[MROWS * DD];
__device__ __align__(128) float g_x[MROWS * DD];

// ---------------- helpers ----------------------------------------------------
__device__ __forceinline__ unsigned packbf(float lo, float hi) {
    unsigned r;
    asm("cvt.rn.bf16x2.f32 %0, %1, %2;" : "=r"(r) : "f"(hi), "f"(lo));
    return r;
}

__device__ __forceinline__ void mma_bf16(float (&c)[4], const unsigned (&a)[4],
                                         unsigned b0, unsigned b1) {
    asm volatile(
        "mma.sync.aligned.m16n8k16.row.col.f32.bf16.bf16.f32 "
        "{%0,%1,%2,%3}, {%4,%5,%6,%7}, {%8,%9}, {%0,%1,%2,%3};\n"
        : "+f"(c[0]), "+f"(c[1]), "+f"(c[2]), "+f"(c[3])
        : "r"(a[0]), "r"(a[1]), "r"(a[2]), "r"(a[3]), "r"(b0), "r"(b1));
}

__device__ __forceinline__ void ldsm4(unsigned (&r)[4], unsigned addr) {
    asm volatile("ldmatrix.sync.aligned.m8n8.x4.shared.b16 {%0,%1,%2,%3}, [%4];"
                 : "=r"(r[0]), "=r"(r[1]), "=r"(r[2]), "=r"(r[3]) : "r"(addr));
}
__device__ __forceinline__ void ldsm4t(unsigned (&r)[4], unsigned addr) {
    asm volatile("ldmatrix.sync.aligned.m8n8.x4.trans.shared.b16 {%0,%1,%2,%3}, [%4];"
                 : "=r"(r[0]), "=r"(r[1]), "=r"(r[2]), "=r"(r[3]) : "r"(addr));
}
__device__ __forceinline__ void cpa16(unsigned s, const void* g) {
    asm volatile("cp.async.cg.shared.global [%0], [%1], 16;" :: "r"(s), "l"(g));
}
__device__ __forceinline__ void cp_commit() {
    asm volatile("cp.async.commit_group;");
}
template <int N>
__device__ __forceinline__ void cp_wait() {
    asm volatile("cp.async.wait_group %0;" :: "n"(N));
}

// ---------------- GEMM: C[M,N] = A[M,K] * W[N,K]^T + bias (+ residual) -------
// Block 256 thr, tile 128x128, BK=32, double-buffered smem, bf16 mma k16.
#define GLD 40   // bf16 elems per smem row (80B stride -> ldmatrix conflict-free)

template <bool ABF, bool OBF, bool RESID>
__device__ __forceinline__ void gemm_body(const void* Av, const float* __restrict__ W,
                                          const float* __restrict__ bias,
                                          const float* __restrict__ R,
                                          void* Cv, int bx, int by) {
    const int K = DD, N = DD;
    __shared__ __nv_bfloat16 As[2][128 * GLD];
    __shared__ __nv_bfloat16 Bs[2][128 * GLD];

    const int tid = threadIdx.x;
    const int warp = tid >> 5, lane = tid & 31;
    const int g = lane >> 2, tg = lane & 3;
    const int wm = (warp >> 2) * 64;
    const int wn = (warp & 3) * 32;
    const int bm0 = bx * 128, bn0 = by * 128;
    const int lrow = lane & 15, lcol = (lane >> 4) << 3;
    const int r_ld = tid >> 3, c_ld = (tid & 7) * 4;

    const unsigned sA = (unsigned)__cvta_generic_to_shared(As);
    const unsigned sB = (unsigned)__cvta_generic_to_shared(Bs);
    const unsigned SZB = 128 * GLD * 2;

    float acc[4][4][4] = {};

    float4 rbw[4];
    float4 raf[4];
    uint2  rab[4];

    auto loadT = [&](int kt) {
        int k0 = kt * 32;
#pragma unroll
        for (int i = 0; i < 4; i++) {
            int r = r_ld + i * 32;
            if (ABF) {
                const __nv_bfloat16* Ab = (const __nv_bfloat16*)Av;
                rab[i] = *reinterpret_cast<const uint2*>(Ab + (size_t)(bm0 + r) * K + k0 + c_ld);
            } else {
                const float* Af = (const float*)Av;
                raf[i] = *reinterpret_cast<const float4*>(Af + (size_t)(bm0 + r) * K + k0 + c_ld);
            }
            rbw[i] = *reinterpret_cast<const float4*>(W + (size_t)(bn0 + r) * K + k0 + c_ld);
        }
    };
    auto storeT = [&](int buf) {
#pragma unroll
        for (int i = 0; i < 4; i++) {
            int r = r_ld + i * 32;
            uint2 ua;
            if (ABF) ua = rab[i];
            else { ua.x = packbf(raf[i].x, raf[i].y); ua.y = packbf(raf[i].z, raf[i].w); }
            *reinterpret_cast<uint2*>(&As[buf][r * GLD + c_ld]) = ua;
            uint2 uw;
            uw.x = packbf(rbw[i].x, rbw[i].y);
            uw.y = packbf(rbw[i].z, rbw[i].w);
            *reinterpret_cast<uint2*>(&Bs[buf][r * GLD + c_ld]) = uw;
        }
    };

    const int NT = K / 32;
    loadT(0);
    storeT(0);
    __syncthreads();
    loadT(1);

    for (int kt = 0; kt < NT; kt++) {
        int cur = kt & 1;
        if (kt + 1 < NT) storeT(1 - cur);
        if (kt + 2 < NT) loadT(kt + 2);
#pragma unroll
        for (int kc = 0; kc < 2; kc++) {
            unsigned a[4][4];
#pragma unroll
            for (int mf = 0; mf < 4; mf++)
                ldsm4(a[mf], sA + cur * SZB +
                              ((wm + mf * 16 + lrow) * GLD + kc * 16 + lcol) * 2);
            unsigned b[2][4];
#pragma unroll
            for (int p = 0; p < 2; p++)
                ldsm4(b[p], sB + cur * SZB +
                             ((wn + p * 16 + lrow) * GLD + kc * 16 + lcol) * 2);
#pragma unroll
            for (int mf = 0; mf < 4; mf++)
#pragma unroll
                for (int nf = 0; nf < 4; nf++)
                    mma_bf16(acc[mf][nf], a[mf], b[nf >> 1][nf & 1], b[nf >> 1][(nf & 1) + 2]);
        }
        __syncthreads();
    }

    // epilogue
#pragma unroll
    for (int mf = 0; mf < 4; mf++) {
        int r0 = bm0 + wm + mf * 16 + g;
        int r1 = r0 + 8;
#pragma unroll
        for (int nf = 0; nf < 4; nf++) {
            int cc = bn0 + wn + nf * 8 + 2 * tg;
            float b0 = bias[cc], b1 = bias[cc + 1];
            float v00 = acc[mf][nf][0] + b0;
            float v01 = acc[mf][nf][1] + b1;
            float v10 = acc[mf][nf][2] + b0;
            float v11 = acc[mf][nf][3] + b1;
            if (OBF) {
                __nv_bfloat16* Cb = (__nv_bfloat16*)Cv;
                *reinterpret_cast<unsigned*>(Cb + (size_t)r0 * N + cc) = packbf(v00, v01);
                *reinterpret_cast<unsigned*>(Cb + (size_t)r1 * N + cc) = packbf(v10, v11);
            } else {
                float* Cf = (float*)Cv;
                if (RESID) {
                    float2 q0 = *reinterpret_cast<const float2*>(R + (size_t)r0 * N + cc);
                    float2 q1 = *reinterpret_cast<const float2*>(R + (size_t)r1 * N + cc);
                    v00 += q0.x; v01 += q0.y; v10 += q1.x; v11 += q1.y;
                }
                *reinterpret_cast<float2*>(Cf + (size_t)r0 * N + cc) = make_float2(v00, v01);
                *reinterpret_cast<float2*>(Cf + (size_t)r1 * N + cc) = make_float2(v10, v11);
            }
        }
    }
}

__global__ void __launch_bounds__(256) qkv_kernel(
    const float* __restrict__ q, const float* __restrict__ k, const float* __restrict__ v,
    const float* __restrict__ Wq, const float* __restrict__ Wk, const float* __restrict__ Wv,
    const float* __restrict__ bq, const float* __restrict__ bk, const float* __restrict__ bv) {
    int z = blockIdx.z;
    const float* A = (z == 0) ? q : (z == 1) ? k : v;
    const float* W = (z == 0) ? Wq : (z == 1) ? Wk : Wv;
    const float* b = (z == 0) ? bq : (z == 1) ? bk : bv;
    __nv_bfloat16* C = (z == 0) ? g_qp : (z == 1) ? g_kp : g_vp;
    gemm_body<false, true, false>(A, W, b, nullptr, C, blockIdx.x, blockIdx.y);
}

__global__ void __launch_bounds__(256) oproj_kernel(const float* __restrict__ q,
                                                    const float* __restrict__ Wo,
                                                    const float* __restrict__ bo) {
    gemm_body<true, false, true>(g_ctx, Wo, bo, q, g_x, blockIdx.x, blockIdx.y);
}

// ---------------- Flash attention (bf16, cp.async, Q-tile 256) ---------------
#define BQ 256
#define BKV 64
#define LDS 72
#define ATT_SMEM_BYTES ((BQ + 2 * BKV + 2 * BKV) * LDS * 2)   // 73728

__global__ void __launch_bounds__(256, 1) attn_kernel() {
    extern __shared__ __align__(16) __nv_bfloat16 sm[];
    __nv_bfloat16* Qs = sm;                           // [256][72]
    __nv_bfloat16* Ks = sm + BQ * LDS;                // 2 x [64][72]
    __nv_bfloat16* Vs = sm + BQ * LDS + 2 * BKV * LDS;

    const int bh = blockIdx.y;
    const int qt = blockIdx.x;
    const __nv_bfloat16* qb = g_qp + (size_t)bh * SS * DKK;
    const __nv_bfloat16* kb = g_kp + (size_t)bh * SS * DKK;
    const __nv_bfloat16* vb = g_vp + (size_t)bh * SS * DKK;
    __nv_bfloat16* ob = g_ctx + (size_t)bh * SS * DKK;

    const int tid = threadIdx.x;
    const int warp = tid >> 5, lane = tid & 31;
    const int g = lane >> 2, tg = lane & 3;
    const int lrow = lane & 15, lcol = (lane >> 4) << 3;
    const int rr = warp * 32;

    const unsigned sQ = (unsigned)__cvta_generic_to_shared(Qs);
    const unsigned sK = (unsigned)__cvta_generic_to_shared(Ks);
    const unsigned sV = (unsigned)__cvta_generic_to_shared(Vs);
    const unsigned KVSZ = BKV * LDS * 2;

    auto loadKV = [&](int kt, int buf) {
#pragma unroll
        for (int i = 0; i < 2; i++) {
            int id = tid + i * 256;
            int r = id >> 3, c8 = id & 7;
            cpa16(sK + buf * KVSZ + (r * LDS + c8 * 8) * 2,
                  kb + (size_t)(kt * BKV + r) * DKK + c8 * 8);
            cpa16(sV + buf * KVSZ + (r * LDS + c8 * 8) * 2,
                  vb + (size_t)(kt * BKV + r) * DKK + c8 * 8);
        }
    };

    // prologue: Q + kv0 -> group0; kv1 -> group1
#pragma unroll
    for (int i = 0; i < 8; i++) {
        int id = tid + i * 256;
        int r = id >> 3, c8 = id & 7;
        cpa16(sQ + (r * LDS + c8 * 8) * 2,
              qb + (size_t)(qt * BQ + r) * DKK + c8 * 8);
    }
    loadKV(0, 0);
    cp_commit();
    loadKV(1, 1);
    cp_commit();

    float o[2][8][4] = {};
    float rmax[4] = {-1e30f, -1e30f, -1e30f, -1e30f};
    float rsum[4] = {};
    const float scale = 0.125f;   // 1/sqrt(64)

    const int NT = SS / BKV;   // 32
    for (int kt = 0; kt < NT; kt++) {
        cp_wait<1>();
        __syncthreads();
        const int cur = kt & 1;

        // ---- S = Q*K^T ----
        float s[2][8][4] = {};
#pragma unroll
        for (int kc = 0; kc < 4; kc++) {
            unsigned qa[2][4];
#pragma unroll
            for (int mf = 0; mf < 2; mf++)
                ldsm4(qa[mf], sQ + ((rr + mf * 16 + lrow) * LDS + kc * 16 + lcol) * 2);
            unsigned kf[4][4];
#pragma unroll
            for (int p = 0; p < 4; p++)
                ldsm4(kf[p], sK + cur * KVSZ + ((p * 16 + lrow) * LDS + kc * 16 + lcol) * 2);
#pragma unroll
            for (int mf = 0; mf < 2; mf++)
#pragma unroll
                for (int nf = 0; nf < 8; nf++)
                    mma_bf16(s[mf][nf], qa[mf], kf[nf >> 1][nf & 1], kf[nf >> 1][(nf & 1) + 2]);
        }

        // ---- online softmax ----
        float mloc[4] = {-1e30f, -1e30f, -1e30f, -1e30f};
#pragma unroll
        for (int mf = 0; mf < 2; mf++)
#pragma unroll
            for (int nf = 0; nf < 8; nf++) {
                s[mf][nf][0] *= scale; s[mf][nf][1] *= scale;
                s[mf][nf][2] *= scale; s[mf][nf][3] *= scale;
                mloc[mf * 2 + 0] = fmaxf(mloc[mf * 2 + 0], fmaxf(s[mf][nf][0], s[mf][nf][1]));
                mloc[mf * 2 + 1] = fmaxf(mloc[mf * 2 + 1], fmaxf(s[mf][nf][2], s[mf][nf][3]));
            }
        float al[4];
#pragma unroll
        for (int j = 0; j < 4; j++) {
            mloc[j] = fmaxf(mloc[j], __shfl_xor_sync(0xffffffffu, mloc[j], 1));
            mloc[j] = fmaxf(mloc[j], __shfl_xor_sync(0xffffffffu, mloc[j], 2));
            float nm = fmaxf(rmax[j], mloc[j]);
            al[j] = __expf(rmax[j] - nm);
            rmax[j] = nm;
        }
        float l[4] = {};
        unsigned pa[2][4][4];
#pragma unroll
        for (int mf = 0; mf < 2; mf++)
#pragma unroll
            for (int nf = 0; nf < 8; nf++) {
                float p0 = __expf(s[mf][nf][0] - rmax[mf * 2 + 0]);
                float p1 = __expf(s[mf][nf][1] - rmax[mf * 2 + 0]);
                float p2 = __expf(s[mf][nf][2] - rmax[mf * 2 + 1]);
                float p3 = __expf(s[mf][nf][3] - rmax[mf * 2 + 1]);
                l[mf * 2 + 0] += p0 + p1;
                l[mf * 2 + 1] += p2 + p3;
                int kc = nf >> 1, off = (nf & 1) * 2;
                pa[mf][kc][off + 0] = packbf(p0, p1);
                pa[mf][kc][off + 1] = packbf(p2, p3);
            }
#pragma unroll
        for (int j = 0; j < 4; j++) {
            l[j] += __shfl_xor_sync(0xffffffffu, l[j], 1);
            l[j] += __shfl_xor_sync(0xffffffffu, l[j], 2);
            rsum[j] = rsum[j] * al[j] + l[j];
        }
#pragma unroll
        for (int mf = 0; mf < 2; mf++)
#pragma unroll
            for (int nf = 0; nf < 8; nf++) {
                o[mf][nf][0] *= al[mf * 2 + 0]; o[mf][nf][1] *= al[mf * 2 + 0];
                o[mf][nf][2] *= al[mf * 2 + 1]; o[mf][nf][3] *= al[mf * 2 + 1];
            }

        // ---- O += P*V ----
#pragma unroll
        for (int kc = 0; kc < 4; kc++) {
            unsigned vf[4][4];
#pragma unroll
            for (int p = 0; p < 4; p++)
                ldsm4t(vf[p], sV + cur * KVSZ + ((kc * 16 + lrow) * LDS + p * 16 + lcol) * 2);
#pragma unroll
            for (int mf = 0; mf < 2; mf++)
#pragma unroll
                for (int nf = 0; nf < 8; nf++)
                    mma_bf16(o[mf][nf], pa[mf][kc],
                             vf[nf >> 1][(nf & 1) * 2], vf[nf >> 1][(nf & 1) * 2 + 1]);
        }

        __syncthreads();
        if (kt + 2 < NT) loadKV(kt + 2, cur);
        cp_commit();
    }

    // ---- write ctx (bf16) ----
    float inv[4];
#pragma unroll
    for (int j = 0; j < 4; j++) inv[j] = 1.f / rsum[j];
#pragma unroll
    for (int mf = 0; mf < 2; mf++) {
        int row0 = qt * BQ + rr + mf * 16 + g;
        int row1 = row0 + 8;
#pragma unroll
        for (int nf = 0; nf < 8; nf++) {
            int cc = nf * 8 + 2 * tg;
            *reinterpret_cast<unsigned*>(ob + (size_t)row0 * DKK + cc) =
                packbf(o[mf][nf][0] * inv[mf * 2 + 0], o[mf][nf][1] * inv[mf * 2 + 0]);
            *reinterpret_cast<unsigned*>(ob + (size_t)row1 * DKK + cc) =
                packbf(o[mf][nf][2] * inv[mf * 2 + 1], o[mf][nf][3] * inv[mf * 2 + 1]);
        }
    }
}

// ---------------- LayerNorm ---------------------------------------------------
__global__ void __launch_bounds__(256) ln_kernel(const float* __restrict__ gamma,
                                                 const float* __restrict__ beta,
                                                 float* __restrict__ out) {
    __shared__ float red[16];
    const int row = blockIdx.x;
    const int tid = threadIdx.x;
    const float* xr = g_x + (size_t)row * DD;
    float4 xv = *reinterpret_cast<const float4*>(xr + tid * 4);
    float s = xv.x + xv.y + xv.z + xv.w;
    float q2 = xv.x * xv.x + xv.y * xv.y + xv.z * xv.z + xv.w * xv.w;
#pragma unroll
    for (int off = 16; off > 0; off >>= 1) {
        s += __shfl_xor_sync(0xffffffffu, s, off);
        q2 += __shfl_xor_sync(0xffffffffu, q2, off);
    }
    int warp = tid >> 5, lane = tid & 31;
    if (lane == 0) { red[warp] = s; red[8 + warp] = q2; }
    __syncthreads();
    if (tid < 32) {
        float ss = (tid < 8) ? red[tid] : 0.f;
        float qq = (tid < 8) ? red[8 + tid] : 0.f;
#pragma unroll
        for (int off = 4; off > 0; off >>= 1) {
            ss += __shfl_xor_sync(0xffffffffu, ss, off);
            qq += __shfl_xor_sync(0xffffffffu, qq, off);
        }
        if (tid == 0) { red[0] = ss; red[1] = qq; }
    }
    __syncthreads();
    float mean = red[0] * (1.f / (float)DD);
    float var = red[1] * (1.f / (float)DD) - mean * mean;
    float inv = rsqrtf(var + 1e-6f);
    int c = tid * 4;
    float4 gv = *reinterpret_cast<const float4*>(gamma + c);
    float4 bv = *reinterpret_cast<const float4*>(beta + c);
    float4 ov;
    ov.x = (xv.x - mean) * inv * gv.x + bv.x;
    ov.y = (xv.y - mean) * inv * gv.y + bv.y;
    ov.z = (xv.z - mean) * inv * gv.z + bv.z;
    ov.w = (xv.w - mean) * inv * gv.w + bv.w;
    *reinterpret_cast<float4*>(out + (size_t)row * DD + c) = ov;
}

// ---------------- launch ------------------------------------------------------
extern "C" void kernel_launch(void* const* d_in, const int* in_sizes, int n_in,
                              void* d_out, int out_size) {
    const float* q     = (const float*)d_in[0];
    const float* k     = (const float*)d_in[1];
    const float* v     = (const float*)d_in[2];
    const float* Wq    = (const float*)d_in[3];
    const float* bq    = (const float*)d_in[4];
    const float* Wk    = (const float*)d_in[5];
    const float* bk    = (const float*)d_in[6];
    const float* Wv    = (const float*)d_in[7];
    const float* bv    = (const float*)d_in[8];
    const float* Wo    = (const float*)d_in[9];
    const float* bo    = (const float*)d_in[10];
    const float* gamma = (const float*)d_in[11];
    const float* beta  = (const float*)d_in[12];
    float* out = (float*)d_out;

    cudaFuncSetAttribute(attn_kernel, cudaFuncAttributeMaxDynamicSharedMemorySize,
                         ATT_SMEM_BYTES);

    qkv_kernel<<<dim3(64, 8, 3), 256>>>(q, k, v, Wq, Wk, Wv, bq, bk, bv);
    attn_kernel<<<dim3(SS / BQ, BB * HH), 256, ATT_SMEM_BYTES>>>();
    oproj_kernel<<<dim3(64, 8), 256>>>(q, Wo, bo);
    ln_kernel<<<MROWS, 256>>>(gamma, beta, out);
}

// round 5
// speedup vs baseline: 2.1228x; 1.0283x over previous
#include <cuda_runtime.h>
#include <cuda_bf16.h>
#include <cstdint>

#define BB   4
#define SS   2048
#define DD   1024
#define HH   16
#define DKK  64
#define MROWS (BB*SS)   // 8192

// ---------------- scratch ----------------------------------------------------
__device__ __align__(128) __nv_bfloat16 g_qi[MROWS * DD];
__device__ __align__(128) __nv_bfloat16 g_ki[MROWS * DD];
__device__ __align__(128) __nv_bfloat16 g_vi[MROWS * DD];
__device__ __align__(128) __nv_bfloat16 g_wq[DD * DD];
__device__ __align__(128) __nv_bfloat16 g_wk[DD * DD];
__device__ __align__(128) __nv_bfloat16 g_wv[DD * DD];
__device__ __align__(128) __nv_bfloat16 g_wo[DD * DD];
__device__ __align__(128) __nv_bfloat16 g_qp[MROWS * DD];
__device__ __align__(128) __nv_bfloat16 g_kp[MROWS * DD];
__device__ __align__(128) __nv_bfloat16 g_vp[MROWS * DD];
__device__ __align__(128) __nv_bfloat16 g_ctx[MROWS * DD];
__device__ __align__(128) float g_x[MROWS * DD];

// ---------------- helpers ----------------------------------------------------
__device__ __forceinline__ unsigned packbf(float lo, float hi) {
    unsigned r;
    asm("cvt.rn.bf16x2.f32 %0, %1, %2;" : "=r"(r) : "f"(hi), "f"(lo));
    return r;
}
__device__ __forceinline__ void mma_bf16(float (&c)[4], const unsigned (&a)[4],
                                         unsigned b0, unsigned b1) {
    asm volatile(
        "mma.sync.aligned.m16n8k16.row.col.f32.bf16.bf16.f32 "
        "{%0,%1,%2,%3}, {%4,%5,%6,%7}, {%8,%9}, {%0,%1,%2,%3};\n"
        : "+f"(c[0]), "+f"(c[1]), "+f"(c[2]), "+f"(c[3])
        : "r"(a[0]), "r"(a[1]), "r"(a[2]), "r"(a[3]), "r"(b0), "r"(b1));
}
__device__ __forceinline__ void ldsm4(unsigned (&r)[4], unsigned addr) {
    asm volatile("ldmatrix.sync.aligned.m8n8.x4.shared.b16 {%0,%1,%2,%3}, [%4];"
                 : "=r"(r[0]), "=r"(r[1]), "=r"(r[2]), "=r"(r[3]) : "r"(addr));
}
__device__ __forceinline__ void ldsm4t(unsigned (&r)[4], unsigned addr) {
    asm volatile("ldmatrix.sync.aligned.m8n8.x4.trans.shared.b16 {%0,%1,%2,%3}, [%4];"
                 : "=r"(r[0]), "=r"(r[1]), "=r"(r[2]), "=r"(r[3]) : "r"(addr));
}
__device__ __forceinline__ void cpa16(unsigned s, const void* g) {
    asm volatile("cp.async.cg.shared.global [%0], [%1], 16;" :: "r"(s), "l"(g));
}
__device__ __forceinline__ void cp_commit() { asm volatile("cp.async.commit_group;"); }
template <int N>
__device__ __forceinline__ void cp_wait() { asm volatile("cp.async.wait_group %0;" :: "n"(N)); }

// ---------------- fp32 -> bf16 convert pass -----------------------------------
__global__ void __launch_bounds__(256) convert_kernel(
    const float* __restrict__ q, const float* __restrict__ k, const float* __restrict__ v,
    const float* __restrict__ Wq, const float* __restrict__ Wk,
    const float* __restrict__ Wv, const float* __restrict__ Wo) {
    const size_t Q4 = (size_t)MROWS * DD / 4;
    const size_t W4 = (size_t)DD * DD / 4;
    size_t i = (size_t)blockIdx.x * blockDim.x + threadIdx.x;
    const float* src;
    __nv_bfloat16* dst;
    size_t off;
    if (i < Q4)            { src = q;  dst = g_qi; off = i; }
    else if (i < 2 * Q4)   { src = k;  dst = g_ki; off = i - Q4; }
    else if (i < 3 * Q4)   { src = v;  dst = g_vi; off = i - 2 * Q4; }
    else {
        size_t w = i - 3 * Q4;
        size_t sel = w / W4;
        off = w - sel * W4;
        src = (sel == 0) ? Wq : (sel == 1) ? Wk : (sel == 2) ? Wv : Wo;
        dst = (sel == 0) ? g_wq : (sel == 1) ? g_wk : (sel == 2) ? g_wv : g_wo;
    }
    float4 xv = *reinterpret_cast<const float4*>(src + off * 4);
    uint2 p;
    p.x = packbf(xv.x, xv.y);
    p.y = packbf(xv.z, xv.w);
    *reinterpret_cast<uint2*>(dst + off * 4) = p;
}

// ---------------- GEMM: C[M,N]=A[M,K]*W[N,K]^T + bias (+resid), 4-stage async -
#define GLD 40            // bf16 per smem row (80B stride, ldsm conflict-free)
#define GSTAGES 4
#define GSTG (128 * GLD * 2)             // bytes per stage per array (10240)
#define GEMM_SMEM (2 * GSTAGES * GSTG)   // 81920

template <bool OBF>
__device__ __forceinline__ void gemm_body(const __nv_bfloat16* __restrict__ A,
                                          const __nv_bfloat16* __restrict__ W,
                                          const float* __restrict__ bias,
                                          const float* __restrict__ R,
                                          void* Cv, int bx, int by) {
    extern __shared__ __align__(16) char gsm[];
    const int tid = threadIdx.x;
    const int warp = tid >> 5, lane = tid & 31;
    const int g = lane >> 2, tg = lane & 3;
    const int wm = (warp >> 2) * 64;
    const int wn = (warp & 3) * 32;
    const int bm0 = bx * 128, bn0 = by * 128;
    const int lrow = lane & 15, lcol = (lane >> 4) << 3;

    const unsigned sA = (unsigned)__cvta_generic_to_shared(gsm);
    const unsigned sB = sA + GSTAGES * GSTG;

    const __nv_bfloat16* Ab = A + (size_t)bm0 * DD;
    const __nv_bfloat16* Wb = W + (size_t)bn0 * DD;

    auto loadT = [&](int kt, int st) {
        const __nv_bfloat16* ga = Ab + kt * 32;
        const __nv_bfloat16* gb = Wb + kt * 32;
#pragma unroll
        for (int j = 0; j < 2; j++) {
            int i = tid + j * 256;
            int r = i >> 2, c16 = i & 3;
            cpa16(sA + st * GSTG + r * 80 + c16 * 16, ga + (size_t)r * DD + c16 * 8);
            cpa16(sB + st * GSTG + r * 80 + c16 * 16, gb + (size_t)r * DD + c16 * 8);
        }
    };

    const int NT = DD / 32;   // 32
    loadT(0, 0); cp_commit();
    loadT(1, 1); cp_commit();
    loadT(2, 2); cp_commit();

    float acc[4][4][4] = {};

    for (int kt = 0; kt < NT; kt++) {
        cp_wait<2>();
        __syncthreads();
        const int st = kt & 3;
        if (kt + 3 < NT) loadT(kt + 3, (kt + 3) & 3);
        cp_commit();
#pragma unroll
        for (int kc = 0; kc < 2; kc++) {
            unsigned a[4][4];
#pragma unroll
            for (int mf = 0; mf < 4; mf++)
                ldsm4(a[mf], sA + st * GSTG +
                              ((wm + mf * 16 + lrow) * GLD + kc * 16 + lcol) * 2);
            unsigned b[2][4];
#pragma unroll
            for (int p = 0; p < 2; p++)
                ldsm4(b[p], sB + st * GSTG +
                             ((wn + p * 16 + lrow) * GLD + kc * 16 + lcol) * 2);
#pragma unroll
            for (int mf = 0; mf < 4; mf++)
#pragma unroll
                for (int nf = 0; nf < 4; nf++)
                    mma_bf16(acc[mf][nf], a[mf], b[nf >> 1][nf & 1], b[nf >> 1][(nf & 1) + 2]);
        }
    }

    // epilogue
#pragma unroll
    for (int mf = 0; mf < 4; mf++) {
        int r0 = bm0 + wm + mf * 16 + g;
        int r1 = r0 + 8;
#pragma unroll
        for (int nf = 0; nf < 4; nf++) {
            int cc = bn0 + wn + nf * 8 + 2 * tg;
            float b0 = bias[cc], b1 = bias[cc + 1];
            float v00 = acc[mf][nf][0] + b0;
            float v01 = acc[mf][nf][1] + b1;
            float v10 = acc[mf][nf][2] + b0;
            float v11 = acc[mf][nf][3] + b1;
            if (OBF) {
                __nv_bfloat16* Cb = (__nv_bfloat16*)Cv;
                *reinterpret_cast<unsigned*>(Cb + (size_t)r0 * DD + cc) = packbf(v00, v01);
                *reinterpret_cast<unsigned*>(Cb + (size_t)r1 * DD + cc) = packbf(v10, v11);
            } else {
                float* Cf = (float*)Cv;
                float2 q0 = *reinterpret_cast<const float2*>(R + (size_t)r0 * DD + cc);
                float2 q1 = *reinterpret_cast<const float2*>(R + (size_t)r1 * DD + cc);
                v00 += q0.x; v01 += q0.y; v10 += q1.x; v11 += q1.y;
                *reinterpret_cast<float2*>(Cf + (size_t)r0 * DD + cc) = make_float2(v00, v01);
                *reinterpret_cast<float2*>(Cf + (size_t)r1 * DD + cc) = make_float2(v10, v11);
            }
        }
    }
}

__global__ void __launch_bounds__(256, 2) qkv_kernel(const float* __restrict__ bq,
                                                     const float* __restrict__ bk,
                                                     const float* __restrict__ bv) {
    int z = blockIdx.z;
    const __nv_bfloat16* A = (z == 0) ? g_qi : (z == 1) ? g_ki : g_vi;
    const __nv_bfloat16* W = (z == 0) ? g_wq : (z == 1) ? g_wk : g_wv;
    const float* bias = (z == 0) ? bq : (z == 1) ? bk : bv;
    __nv_bfloat16* C = (z == 0) ? g_qp : (z == 1) ? g_kp : g_vp;
    gemm_body<true>(A, W, bias, nullptr, C, blockIdx.x, blockIdx.y);
}

__global__ void __launch_bounds__(256, 2) oproj_kernel(const float* __restrict__ q,
                                                       const float* __restrict__ bo) {
    gemm_body<false>(g_ctx, g_wo, bo, q, g_x, blockIdx.x, blockIdx.y);
}

// ---------------- Flash attention (bf16, cp.async, Q-tile 256, Q-frag hoist) -
#define BQ 256
#define BKV 64
#define LDS 72
#define ATT_SMEM_BYTES ((BQ + 2 * BKV + 2 * BKV) * LDS * 2)   // 73728

__global__ void __launch_bounds__(256, 1) attn_kernel() {
    extern __shared__ __align__(16) __nv_bfloat16 sm[];
    __nv_bfloat16* Qs = sm;
    __nv_bfloat16* Ks = sm + BQ * LDS;
    __nv_bfloat16* Vs = sm + BQ * LDS + 2 * BKV * LDS;

    const int bh = blockIdx.y;
    const int qt = blockIdx.x;
    const __nv_bfloat16* qb = g_qp + (size_t)bh * SS * DKK;
    const __nv_bfloat16* kb = g_kp + (size_t)bh * SS * DKK;
    const __nv_bfloat16* vb = g_vp + (size_t)bh * SS * DKK;
    __nv_bfloat16* ob = g_ctx + (size_t)bh * SS * DKK;

    const int tid = threadIdx.x;
    const int warp = tid >> 5, lane = tid & 31;
    const int g = lane >> 2, tg = lane & 3;
    const int lrow = lane & 15, lcol = (lane >> 4) << 3;
    const int rr = warp * 32;

    const unsigned sQ = (unsigned)__cvta_generic_to_shared(Qs);
    const unsigned sK = (unsigned)__cvta_generic_to_shared(Ks);
    const unsigned sV = (unsigned)__cvta_generic_to_shared(Vs);
    const unsigned KVSZ = BKV * LDS * 2;

    auto loadKV = [&](int kt, int buf) {
#pragma unroll
        for (int i = 0; i < 2; i++) {
            int id = tid + i * 256;
            int r = id >> 3, c8 = id & 7;
            cpa16(sK + buf * KVSZ + (r * LDS + c8 * 8) * 2,
                  kb + (size_t)(kt * BKV + r) * DKK + c8 * 8);
            cpa16(sV + buf * KVSZ + (r * LDS + c8 * 8) * 2,
                  vb + (size_t)(kt * BKV + r) * DKK + c8 * 8);
        }
    };

#pragma unroll
    for (int i = 0; i < 8; i++) {
        int id = tid + i * 256;
        int r = id >> 3, c8 = id & 7;
        cpa16(sQ + (r * LDS + c8 * 8) * 2,
              qb + (size_t)(qt * BQ + r) * DKK + c8 * 8);
    }
    loadKV(0, 0);
    cp_commit();
    loadKV(1, 1);
    cp_commit();

    // hoist Q fragments (loop-invariant)
    cp_wait<1>();
    __syncthreads();
    unsigned qa[2][4][4];
#pragma unroll
    for (int mf = 0; mf < 2; mf++)
#pragma unroll
        for (int kc = 0; kc < 4; kc++)
            ldsm4(qa[mf][kc], sQ + ((rr + mf * 16 + lrow) * LDS + kc * 16 + lcol) * 2);

    float o[2][8][4] = {};
    float rmax[4] = {-1e30f, -1e30f, -1e30f, -1e30f};
    float rsum[4] = {};
    const float scale = 0.125f;

    const int NT = SS / BKV;
    for (int kt = 0; kt < NT; kt++) {
        cp_wait<1>();
        __syncthreads();
        const int cur = kt & 1;

        float s[2][8][4] = {};
#pragma unroll
        for (int kc = 0; kc < 4; kc++) {
            unsigned kf[4][4];
#pragma unroll
            for (int p = 0; p < 4; p++)
                ldsm4(kf[p], sK + cur * KVSZ + ((p * 16 + lrow) * LDS + kc * 16 + lcol) * 2);
#pragma unroll
            for (int mf = 0; mf < 2; mf++)
#pragma unroll
                for (int nf = 0; nf < 8; nf++)
                    mma_bf16(s[mf][nf], qa[mf][kc], kf[nf >> 1][nf & 1], kf[nf >> 1][(nf & 1) + 2]);
        }

        float mloc[4] = {-1e30f, -1e30f, -1e30f, -1e30f};
#pragma unroll
        for (int mf = 0; mf < 2; mf++)
#pragma unroll
            for (int nf = 0; nf < 8; nf++) {
                s[mf][nf][0] *= scale; s[mf][nf][1] *= scale;
                s[mf][nf][2] *= scale; s[mf][nf][3] *= scale;
                mloc[mf * 2 + 0] = fmaxf(mloc[mf * 2 + 0], fmaxf(s[mf][nf][0], s[mf][nf][1]));
                mloc[mf * 2 + 1] = fmaxf(mloc[mf * 2 + 1], fmaxf(s[mf][nf][2], s[mf][nf][3]));
            }
        float al[4];
#pragma unroll
        for (int j = 0; j < 4; j++) {
            mloc[j] = fmaxf(mloc[j], __shfl_xor_sync(0xffffffffu, mloc[j], 1));
            mloc[j] = fmaxf(mloc[j], __shfl_xor_sync(0xffffffffu, mloc[j], 2));
            float nm = fmaxf(rmax[j], mloc[j]);
            al[j] = __expf(rmax[j] - nm);
            rmax[j] = nm;
        }
        float l[4] = {};
        unsigned pa[2][4][4];
#pragma unroll
        for (int mf = 0; mf < 2; mf++)
#pragma unroll
            for (int nf = 0; nf < 8; nf++) {
                float p0 = __expf(s[mf][nf][0] - rmax[mf * 2 + 0]);
                float p1 = __expf(s[mf][nf][1] - rmax[mf * 2 + 0]);
                float p2 = __expf(s[mf][nf][2] - rmax[mf * 2 + 1]);
                float p3 = __expf(s[mf][nf][3] - rmax[mf * 2 + 1]);
                l[mf * 2 + 0] += p0 + p1;
                l[mf * 2 + 1] += p2 + p3;
                int kc = nf >> 1, off = (nf & 1) * 2;
                pa[mf][kc][off + 0] = packbf(p0, p1);
                pa[mf][kc][off + 1] = packbf(p2, p3);
            }
#pragma unroll
        for (int j = 0; j < 4; j++) {
            l[j] += __shfl_xor_sync(0xffffffffu, l[j], 1);
            l[j] += __shfl_xor_sync(0xffffffffu, l[j], 2);
            rsum[j] = rsum[j] * al[j] + l[j];
        }
#pragma unroll
        for (int mf = 0; mf < 2; mf++)
#pragma unroll
            for (int nf = 0; nf < 8; nf++) {
                o[mf][nf][0] *= al[mf * 2 + 0]; o[mf][nf][1] *= al[mf * 2 + 0];
                o[mf][nf][2] *= al[mf * 2 + 1]; o[mf][nf][3] *= al[mf * 2 + 1];
            }

#pragma unroll
        for (int kc = 0; kc < 4; kc++) {
            unsigned vf[4][4];
#pragma unroll
            for (int p = 0; p < 4; p++)
                ldsm4t(vf[p], sV + cur * KVSZ + ((kc * 16 + lrow) * LDS + p * 16 + lcol) * 2);
#pragma unroll
            for (int mf = 0; mf < 2; mf++)
#pragma unroll
                for (int nf = 0; nf < 8; nf++)
                    mma_bf16(o[mf][nf], pa[mf][kc],
                             vf[nf >> 1][(nf & 1) * 2], vf[nf >> 1][(nf & 1) * 2 + 1]);
        }

        __syncthreads();
        if (kt + 2 < NT) loadKV(kt + 2, cur);
        cp_commit();
    }

    float inv[4];
#pragma unroll
    for (int j = 0; j < 4; j++) inv[j] = 1.f / rsum[j];
#pragma unroll
    for (int mf = 0; mf < 2; mf++) {
        int row0 = qt * BQ + rr + mf * 16 + g;
        int row1 = row0 + 8;
#pragma unroll
        for (int nf = 0; nf < 8; nf++) {
            int cc = nf * 8 + 2 * tg;
            *reinterpret_cast<unsigned*>(ob + (size_t)row0 * DKK + cc) =
                packbf(o[mf][nf][0] * inv[mf * 2 + 0], o[mf][nf][1] * inv[mf * 2 + 0]);
            *reinterpret_cast<unsigned*>(ob + (size_t)row1 * DKK + cc) =
                packbf(o[mf][nf][2] * inv[mf * 2 + 1], o[mf][nf][3] * inv[mf * 2 + 1]);
        }
    }
}

// ---------------- LayerNorm ---------------------------------------------------
__global__ void __launch_bounds__(256) ln_kernel(const float* __restrict__ gamma,
                                                 const float* __restrict__ beta,
                                                 float* __restrict__ out) {
    __shared__ float red[16];
    const int row = blockIdx.x;
    const int tid = threadIdx.x;
    const float* xr = g_x + (size_t)row * DD;
    float4 xv = *reinterpret_cast<const float4*>(xr + tid * 4);
    float s = xv.x + xv.y + xv.z + xv.w;
    float q2 = xv.x * xv.x + xv.y * xv.y + xv.z * xv.z + xv.w * xv.w;
#pragma unroll
    for (int off = 16; off > 0; off >>= 1) {
        s += __shfl_xor_sync(0xffffffffu, s, off);
        q2 += __shfl_xor_sync(0xffffffffu, q2, off);
    }
    int warp = tid >> 5, lane = tid & 31;
    if (lane == 0) { red[warp] = s; red[8 + warp] = q2; }
    __syncthreads();
    if (tid < 32) {
        float ss = (tid < 8) ? red[tid] : 0.f;
        float qq = (tid < 8) ? red[8 + tid] : 0.f;
#pragma unroll
        for (int off = 4; off > 0; off >>= 1) {
            ss += __shfl_xor_sync(0xffffffffu, ss, off);
            qq += __shfl_xor_sync(0xffffffffu, qq, off);
        }
        if (tid == 0) { red[0] = ss; red[1] = qq; }
    }
    __syncthreads();
    float mean = red[0] * (1.f / (float)DD);
    float var = red[1] * (1.f / (float)DD) - mean * mean;
    float inv = rsqrtf(var + 1e-6f);
    int c = tid * 4;
    float4 gv = *reinterpret_cast<const float4*>(gamma + c);
    float4 bv = *reinterpret_cast<const float4*>(beta + c);
    float4 ov;
    ov.x = (xv.x - mean) * inv * gv.x + bv.x;
    ov.y = (xv.y - mean) * inv * gv.y + bv.y;
    ov.z = (xv.z - mean) * inv * gv.z + bv.z;
    ov.w = (xv.w - mean) * inv * gv.w + bv.w;
    *reinterpret_cast<float4*>(out + (size_t)row * DD + c) = ov;
}

// ---------------- launch ------------------------------------------------------
extern "C" void kernel_launch(void* const* d_in, const int* in_sizes, int n_in,
                              void* d_out, int out_size) {
    const float* q     = (const float*)d_in[0];
    const float* k     = (const float*)d_in[1];
    const float* v     = (const float*)d_in[2];
    const float* Wq    = (const float*)d_in[3];
    const float* bq    = (const float*)d_in[4];
    const float* Wk    = (const float*)d_in[5];
    const float* bk    = (const float*)d_in[6];
    const float* Wv    = (const float*)d_in[7];
    const float* bv    = (const float*)d_in[8];
    const float* Wo    = (const float*)d_in[9];
    const float* bo    = (const float*)d_in[10];
    const float* gamma = (const float*)d_in[11];
    const float* beta  = (const float*)d_in[12];
    float* out = (float*)d_out;

    cudaFuncSetAttribute(attn_kernel, cudaFuncAttributeMaxDynamicSharedMemorySize,
                         ATT_SMEM_BYTES);
    cudaFuncSetAttribute(qkv_kernel, cudaFuncAttributeMaxDynamicSharedMemorySize,
                         GEMM_SMEM);
    cudaFuncSetAttribute(oproj_kernel, cudaFuncAttributeMaxDynamicSharedMemorySize,
                         GEMM_SMEM);

    convert_kernel<<<28672, 256>>>(q, k, v, Wq, Wk, Wv, Wo);
    qkv_kernel<<<dim3(64, 8, 3), 256, GEMM_SMEM>>>(bq, bk, bv);
    attn_kernel<<<dim3(SS / BQ, BB * HH), 256, ATT_SMEM_BYTES>>>();
    oproj_kernel<<<dim3(64, 8), 256, GEMM_SMEM>>>(q, bo);
    ln_kernel<<<MROWS, 256>>>(gamma, beta, out);
}